// round 14
// baseline (speedup 1.0000x reference)
#include <cuda_runtime.h>
#include <cuda_fp16.h>
#include <cstdint>

// ---------------- problem constants ----------------
#define TOKENS   32768
#define HIDDEN   5120
#define NEXP     160
#define NGROUP   8
#define EPG      20
#define TOPK     6
#define KCHUNK   64
#define NCHUNKS  80
#define NTILES   256              // 32768 / 128
#define NTHREADS 256
#define LO_SCALE 2048.0f
#define LO_INV   (1.0f / 2048.0f)

// ---------------- smem layout ----------------
#define SA_OFF(buf, hl) ((buf) * 32768 + (hl) * 16384)
#define SB_OFF(buf, hl) (65536 + (buf) * 40960 + (hl) * 20480)
#define SMEM_BYTES 188416
#define BTILE_BYTES 20480
#define RED_OFF 86016           // 2 x 128 floats
#define G8_OFF  87040           // 8 x 128 floats

#define SWZ(o) ((uint32_t)(o) ^ (((uint32_t)(o) >> 3) & 0x70))

// ---------------- device scratch ----------------
__device__ __align__(16) unsigned char g_whi[NCHUNKS * BTILE_BYTES];
__device__ __align__(16) unsigned char g_wlo[NCHUNKS * BTILE_BYTES];
__device__ __align__(16) float g_part[NTILES * 2 * 128 * NEXP];
__device__ int g_done[NTILES];

// ---------------- helpers ----------------
__device__ __forceinline__ uint32_t smem_u32(const void* p) {
    uint32_t a;
    asm("{ .reg .u64 t; cvta.to.shared.u64 t, %1; cvt.u32.u64 %0, t; }"
        : "=r"(a) : "l"(p));
    return a;
}
__device__ __forceinline__ uint32_t h2_bits(__half2 h) {
    return *reinterpret_cast<uint32_t*>(&h);
}
__device__ __forceinline__ int owner(int w) {
    return (w < 7784) ? (w / 139) : ((w - 56) / 138);
}

#define LDSM_X4(r0, r1, r2, r3, addr) \
    asm volatile("ldmatrix.sync.aligned.m8n8.x4.shared.b16 {%0,%1,%2,%3}, [%4];" \
                 : "=r"(r0), "=r"(r1), "=r"(r2), "=r"(r3) : "r"(addr))
#define MMA_F32(d, a0, a1, a2, a3, b0, b1) \
    asm("mma.sync.aligned.m16n8k16.row.col.f32.f16.f16.f32 " \
        "{%0,%1,%2,%3}, {%4,%5,%6,%7}, {%8,%9}, {%0,%1,%2,%3};" \
        : "+f"((d)[0]), "+f"((d)[1]), "+f"((d)[2]), "+f"((d)[3]) \
        : "r"(a0), "r"(a1), "r"(a2), "r"(a3), "r"(b0), "r"(b1))
#define MMA_F16(d, a0, a1, a2, a3, b0, b1) \
    asm("mma.sync.aligned.m16n8k16.row.col.f16.f16.f16.f16 " \
        "{%0,%1}, {%2,%3,%4,%5}, {%6,%7}, {%0,%1};" \
        : "+r"((d)[0]), "+r"((d)[1]) \
        : "r"(a0), "r"(a1), "r"(a2), "r"(a3), "r"(b0), "r"(b1))
#define CP_ASYNC16(saddr, gptr) \
    asm volatile("cp.async.cg.shared.global [%0], [%1], 16;" \
                 :: "r"(saddr), "l"(gptr))
#define CP_COMMIT() asm volatile("cp.async.commit_group;" ::: "memory")
#define CP_WAIT0()  asm volatile("cp.async.wait_group 0;" ::: "memory")
#define CP_WAIT1()  asm volatile("cp.async.wait_group 1;" ::: "memory")

// ---------------- prep: split W + zero done counters ------------------------
__global__ void prep_w_kernel(const float* __restrict__ w) {
    int idx = blockIdx.x * 256 + threadIdx.x;
    if (idx < NTILES) g_done[idx] = 0;
    if (idx >= NEXP * (HIDDEN / 8)) return;
    int n  = idx / (HIDDEN / 8);
    int k8 = idx - n * (HIDDEN / 8);
    int k  = k8 * 8;
    const float4* src = reinterpret_cast<const float4*>(w + (size_t)n * HIDDEN + k);
    float4 v0 = src[0], v1 = src[1];
    float f[8] = {v0.x, v0.y, v0.z, v0.w, v1.x, v1.y, v1.z, v1.w};

    uint32_t hh[4], ll[4];
#pragma unroll
    for (int i = 0; i < 4; ++i) {
        __half2 h = __floats2half2_rn(f[2 * i], f[2 * i + 1]);
        hh[i] = h2_bits(h);
        float2 hf = __half22float2(h);
        __half2 l = __floats2half2_rn((f[2 * i]     - hf.x) * LO_SCALE,
                                      (f[2 * i + 1] - hf.y) * LO_SCALE);
        ll[i] = h2_bits(l);
    }
    int c   = k >> 6;
    int col = k & 63;
    uint32_t sw = SWZ(n * 128 + col * 2);
    *reinterpret_cast<uint4*>(g_whi + (size_t)c * BTILE_BYTES + sw) =
        make_uint4(hh[0], hh[1], hh[2], hh[3]);
    *reinterpret_cast<uint4*>(g_wlo + (size_t)c * BTILE_BYTES + sw) =
        make_uint4(ll[0], ll[1], ll[2], ll[3]);
}

// ---------------- A convert + swizzled store helper -------------------------
__device__ __forceinline__ void cvt_store_a(char* smem, int bufA,
                                            const float4* xv, const uint32_t* sts_off,
                                            int it0, int it1) {
#pragma unroll
    for (int it = 0; it < 8; ++it) {
        if (it < it0 || it >= it1) continue;
        float4 v = xv[it];
        __half2 h01 = __floats2half2_rn(v.x, v.y);
        __half2 h23 = __floats2half2_rn(v.z, v.w);
        float2 f01 = __half22float2(h01);
        float2 f23 = __half22float2(h23);
        __half2 l01 = __floats2half2_rn((v.x - f01.x) * LO_SCALE, (v.y - f01.y) * LO_SCALE);
        __half2 l23 = __floats2half2_rn((v.z - f23.x) * LO_SCALE, (v.w - f23.y) * LO_SCALE);
        *reinterpret_cast<uint2*>(smem + SA_OFF(bufA, 0) + sts_off[it]) =
            make_uint2(h2_bits(h01), h2_bits(h23));
        *reinterpret_cast<uint2*>(smem + SA_OFF(bufA, 1) + sts_off[it]) =
            make_uint2(h2_bits(l01), h2_bits(l23));
    }
}

// ---------------- main fused kernel ----------------------------------------
__global__ __launch_bounds__(NTHREADS, 1)
void moe_gate_kernel(const float* __restrict__ x, float* __restrict__ out) {
    extern __shared__ __align__(1024) char smem[];
    __shared__ int flag_s;
    const uint32_t sb = smem_u32(smem);
    const int tid  = threadIdx.x;
    const int lane = tid & 31;
    const int wid  = tid >> 5;
    const int wm   = wid >> 2;
    const int wn   = wid & 3;
    const int swoff = wm * 2;

    const int g  = tid & 15;
    const int rg = tid >> 4;

    uint32_t sts_off[8];
#pragma unroll
    for (int it = 0; it < 8; ++it) {
        int row = rg + it * 16;
        sts_off[it] = (uint32_t)(row * 128) + (((uint32_t)(g * 8)) ^ ((uint32_t)(row & 7) << 4));
    }

    const int grp = lane >> 3;
    const int lr  = lane & 7;

    uint32_t a_row_off[4], a_swm[4];
#pragma unroll
    for (int mi = 0; mi < 4; ++mi) {
        int row = wm * 64 + mi * 16 + (grp & 1) * 8 + lr;
        a_row_off[mi] = (uint32_t)(row * 128);
        a_swm[mi]     = (uint32_t)(row & 7) << 4;
    }
    const int a_segadd = (grp >> 1);

    uint32_t b_row_off[2], b_swm[2];
#pragma unroll
    for (int p = 0; p < 2; ++p) {
        int n = wn * 40 + p * 16 + (grp >> 1) * 8 + lr;
        b_row_off[p] = (uint32_t)(n * 128);
        b_swm[p]     = (uint32_t)(n & 7) << 4;
    }
    const int b_segadd = (grp & 1);
    // merged tail: lanes 0-15 address the hi tile, lanes 16-31 the lo tile
    int n2 = wn * 40 + 32 + ((lane & 15) & 7);
    const uint32_t b2_row_off = (uint32_t)(n2 * 128);
    const uint32_t b2_swm     = (uint32_t)(n2 & 7) << 4;
    const int b2_segadd = ((lane & 15) >> 3);
    const int tail_hi   = (lane < 16);

    const int bid   = blockIdx.x;
    const int start = (bid < 56) ? 139 * bid : 138 * bid + 56;
    const int cnt   = (bid < 56) ? 139 : 138;
    const int wend  = start + cnt;

    int w = start;
    while (w < wend) {
        const int t  = w / NCHUNKS;
        const int c0 = w - NCHUNKS * t;
        const int c1 = min(wend - NCHUNKS * t, NCHUNKS);
        const int m0 = t * 128;
        const float* xbase = x + (size_t)(m0 + rg) * HIDDEN + g * 4;

        float    facc[4][5][4];
        uint32_t hacc[4][5][2];
#pragma unroll
        for (int mi = 0; mi < 4; ++mi)
#pragma unroll
            for (int nj = 0; nj < 5; ++nj) {
#pragma unroll
                for (int q = 0; q < 4; ++q) facc[mi][nj][q] = 0.f;
                hacc[mi][nj][0] = 0u; hacc[mi][nj][1] = 0u;
            }
        float4 xv[8];

        __syncthreads();    // smem free from previous segment / epilogue
        // ---------------- prologue: stage B(c0)[,B(c0+1)], A(c0) -----------
        {
#pragma unroll
            for (int i = 0; i < 5; ++i) {
                uint32_t o = (uint32_t)(i * 256 + tid) * 16;
                CP_ASYNC16(sb + SB_OFF(0, 0) + o, g_whi + (size_t)c0 * BTILE_BYTES + o);
                CP_ASYNC16(sb + SB_OFF(0, 1) + o, g_wlo + (size_t)c0 * BTILE_BYTES + o);
            }
            CP_COMMIT();
            const bool two = (c0 + 1 < c1);
            if (two) {
#pragma unroll
                for (int i = 0; i < 5; ++i) {
                    uint32_t o = (uint32_t)(i * 256 + tid) * 16;
                    CP_ASYNC16(sb + SB_OFF(1, 0) + o, g_whi + (size_t)(c0 + 1) * BTILE_BYTES + o);
                    CP_ASYNC16(sb + SB_OFF(1, 1) + o, g_wlo + (size_t)(c0 + 1) * BTILE_BYTES + o);
                }
                CP_COMMIT();
            }
#pragma unroll
            for (int it = 0; it < 8; ++it)
                xv[it] = *reinterpret_cast<const float4*>(
                    xbase + (size_t)c0 * KCHUNK + (size_t)(it * 16) * HIDDEN);
            cvt_store_a(smem, 0, xv, sts_off, 0, 8);
            if (two) CP_WAIT1(); else CP_WAIT0();
            __syncthreads();
        }

        // ---------------- segment main loop ----------------
        int bufB = 0, bufA = 0;
        for (int c = c0; c < c1; ++c) {
            const bool more = (c + 1 < c1);
            // issue B(c+2): safe — full barrier ended chunk c-1, its buffer is free
            if (c + 2 < c1) {
                int bw = bufB + 2; if (bw >= 3) bw -= 3;
                const size_t bo = (size_t)(c + 2) * BTILE_BYTES;
#pragma unroll
                for (int i = 0; i < 5; ++i) {
                    uint32_t o = (uint32_t)(i * 256 + tid) * 16;
                    CP_ASYNC16(sb + SB_OFF(bw, 0) + o, g_whi + bo + o);
                    CP_ASYNC16(sb + SB_OFF(bw, 1) + o, g_wlo + bo + o);
                }
                CP_COMMIT();
            }
            if (more) {
                const float* xc = xbase + (size_t)(c + 1) * KCHUNK;
#pragma unroll
                for (int it = 0; it < 8; ++it)
                    xv[it] = *reinterpret_cast<const float4*>(xc + (size_t)(it * 16) * HIDDEN);
            }

            const uint32_t aHi = sb + SA_OFF(bufA, 0);
            const uint32_t aLo = sb + SA_OFF(bufA, 1);
            const uint32_t bHi = sb + SB_OFF(bufB, 0);
            const uint32_t bLo = sb + SB_OFF(bufB, 1);

#pragma unroll
            for (int s = 0; s < 4; ++s) {
                const int sidx = (s + swoff) & 3;
                uint32_t bh[10], bl[10];
#pragma unroll
                for (int p = 0; p < 2; ++p) {
                    uint32_t seg = (uint32_t)(2 * sidx + b_segadd) << 4;
                    uint32_t off = b_row_off[p] + (seg ^ b_swm[p]);
                    LDSM_X4(bh[4 * p + 0], bh[4 * p + 1], bh[4 * p + 2], bh[4 * p + 3], bHi + off);
                    LDSM_X4(bl[4 * p + 0], bl[4 * p + 1], bl[4 * p + 2], bl[4 * p + 3], bLo + off);
                }
                {   // merged hi/lo tail (lanes 0-15: hi, 16-31: lo)
                    uint32_t seg = (uint32_t)(2 * sidx + b2_segadd) << 4;
                    uint32_t off = b2_row_off + (seg ^ b2_swm);
                    uint32_t base = tail_hi ? bHi : bLo;
                    LDSM_X4(bh[8], bh[9], bl[8], bl[9], base + off);
                }
#pragma unroll
                for (int mi = 0; mi < 4; ++mi) {
                    uint32_t seg = (uint32_t)(2 * sidx + a_segadd) << 4;
                    uint32_t off = a_row_off[mi] + (seg ^ a_swm[mi]);
                    uint32_t ah0, ah1, ah2, ah3, al0, al1, al2, al3;
                    LDSM_X4(ah0, ah1, ah2, ah3, aHi + off);
                    LDSM_X4(al0, al1, al2, al3, aLo + off);
#pragma unroll
                    for (int nj = 0; nj < 5; ++nj)
                        MMA_F32(facc[mi][nj], ah0, ah1, ah2, ah3, bh[2 * nj], bh[2 * nj + 1]);
#pragma unroll
                    for (int nj = 0; nj < 5; ++nj)
                        MMA_F16(hacc[mi][nj], ah0, ah1, ah2, ah3, bl[2 * nj], bl[2 * nj + 1]);
#pragma unroll
                    for (int nj = 0; nj < 5; ++nj)
                        MMA_F16(hacc[mi][nj], al0, al1, al2, al3, bh[2 * nj], bh[2 * nj + 1]);
                }
                // wm-staggered producer bursts: the two warps of an SMSP have
                // different wm, so one warp always keeps the tensor pipe fed
                // while the other runs its convert+STS burst.
                if (more) {
                    if (wm == 0) {
                        if (s == 1) cvt_store_a(smem, bufA ^ 1, xv, sts_off, 0, 4);
                        if (s == 3) cvt_store_a(smem, bufA ^ 1, xv, sts_off, 4, 8);
                    } else {
                        if (s == 2) cvt_store_a(smem, bufA ^ 1, xv, sts_off, 0, 8);
                    }
                }
            }

            if (c + 2 < c1)      CP_WAIT1();
            else if (more)       CP_WAIT0();
            __syncthreads();
            bufA ^= 1;
            bufB += 1; if (bufB >= 3) bufB -= 3;
        }

        // ---------------- write partial logits to global slot ---------------
        const int b0own = owner(NCHUNKS * t);
        const int slot  = bid - b0own;
        float* gp = g_part + ((size_t)t * 2 + slot) * (128 * NEXP);
#pragma unroll
        for (int mi = 0; mi < 4; ++mi) {
            int r0 = wm * 64 + mi * 16 + (lane >> 2);
#pragma unroll
            for (int nj = 0; nj < 5; ++nj) {
                int cb = wn * 40 + nj * 8 + (lane & 3) * 2;
                float2 c0v = __half22float2(*reinterpret_cast<__half2*>(&hacc[mi][nj][0]));
                float2 c1v = __half22float2(*reinterpret_cast<__half2*>(&hacc[mi][nj][1]));
                *reinterpret_cast<float2*>(gp + (size_t)r0 * NEXP + cb) =
                    make_float2(facc[mi][nj][0] + c0v.x * LO_INV,
                                facc[mi][nj][1] + c0v.y * LO_INV);
                *reinterpret_cast<float2*>(gp + (size_t)(r0 + 8) * NEXP + cb) =
                    make_float2(facc[mi][nj][2] + c1v.x * LO_INV,
                                facc[mi][nj][3] + c1v.y * LO_INV);
            }
        }
        __threadfence();
        if (tid == 0) {
            int nctr = owner(NCHUNKS * t + NCHUNKS - 1) - b0own + 1;
            int old = atomicAdd(&g_done[t], 1);
            flag_s = (old == nctr - 1) ? nctr : 0;
        }
        __syncthreads();
        const int n_contrib = flag_s;

        // ---------------- epilogue (last finisher only) ----------------------
        if (n_contrib) {
            __threadfence();
            float* red = reinterpret_cast<float*>(smem + RED_OFF);
            float* g8  = reinterpret_cast<float*>(smem + G8_OFF);
            const int tok = tid & 127;
            const int seg = tid >> 7;
            const int e0  = seg * 80;
            const float* gp0 = g_part + (size_t)t * 2 * (128 * NEXP) + (size_t)tok * NEXP + e0;

            float z[80];
#pragma unroll
            for (int j = 0; j < 80; j += 2) {
                float2 v = __ldcg(reinterpret_cast<const float2*>(gp0 + j));
                if (n_contrib == 2) {
                    float2 v2 = __ldcg(reinterpret_cast<const float2*>(gp0 + 128 * NEXP + j));
                    v.x += v2.x; v.y += v2.y;
                }
                z[j] = v.x; z[j + 1] = v.y;
            }

            float mx = -3.4e38f;
#pragma unroll
            for (int j = 0; j < 80; ++j) mx = fmaxf(mx, z[j]);
            red[seg * 128 + tok] = mx;
            __syncthreads();
            mx = fmaxf(red[tok], red[128 + tok]);
            __syncthreads();

            float sum = 0.f;
#pragma unroll
            for (int j = 0; j < 80; ++j) {
                float p = __expf(z[j] - mx);
                sum += p;
                z[j] = p;
            }
            red[seg * 128 + tok] = sum;
            __syncthreads();
            sum = red[tok] + red[128 + tok];

            float gm[4];
#pragma unroll
            for (int q = 0; q < 4; ++q) {
                float m = 0.f;
#pragma unroll
                for (int tt = 0; tt < EPG; ++tt) m = fmaxf(m, z[q * EPG + tt]);
                gm[q] = m;
                g8[(seg * 4 + q) * 128 + tok] = m;
            }
            __syncthreads();

            float gv[NGROUP];
#pragma unroll
            for (int q = 0; q < NGROUP; ++q) gv[q] = g8[q * 128 + tok];
            float t1 = 0.f, t2 = 0.f, t3 = 0.f;
#pragma unroll
            for (int q = 0; q < NGROUP; ++q) t1 = fmaxf(t1, gv[q]);
#pragma unroll
            for (int q = 0; q < NGROUP; ++q) t2 = fmaxf(t2, (gv[q] < t1) ? gv[q] : 0.f);
#pragma unroll
            for (int q = 0; q < NGROUP; ++q) t3 = fmaxf(t3, (gv[q] < t2) ? gv[q] : 0.f);

#pragma unroll
            for (int q = 0; q < 4; ++q) {
                float keep = (gm[q] >= t3) ? 1.f : 0.f;
#pragma unroll
                for (int tt = 0; tt < EPG; ++tt) z[q * EPG + tt] *= keep;
            }

            const float inv = 16.0f / sum;
            float* orow = out + (size_t)(m0 + tok) * TOPK;
            float prev = 3.4e38f;
            __syncthreads();
            for (int i = 0; i < TOPK; ++i) {
                float cand = 0.f;
#pragma unroll
                for (int j = 0; j < 80; ++j)
                    cand = fmaxf(cand, (z[j] < prev) ? z[j] : 0.f);
                red[seg * 128 + tok] = cand;
                __syncthreads();
                float cur = fmaxf(red[tok], red[128 + tok]);
                __syncthreads();
                if (seg == 0) orow[i] = cur * inv;
                prev = cur;
            }
        }

        w = NCHUNKS * t + c1;
    }
}

// ---------------- launch ----------------------------------------------------
extern "C" void kernel_launch(void* const* d_in, const int* in_sizes, int n_in,
                              void* d_out, int out_size) {
    const float* x = (const float*)d_in[0];   // [32768, 5120] fp32
    const float* w = (const float*)d_in[1];   // [160, 5120] fp32
    float* out = (float*)d_out;               // [32768, 6] fp32

    cudaFuncSetAttribute(moe_gate_kernel,
                         cudaFuncAttributeMaxDynamicSharedMemorySize, SMEM_BYTES);

    int prep_elems = NEXP * (HIDDEN / 8);
    prep_w_kernel<<<(prep_elems + 255) / 256, 256>>>(w);
    moe_gate_kernel<<<148, NTHREADS, SMEM_BYTES>>>(x, out);
}

// round 15
// speedup vs baseline: 1.0034x; 1.0034x over previous
#include <cuda_runtime.h>
#include <cuda_fp16.h>
#include <cstdint>

// ---------------- problem constants ----------------
#define TOKENS   32768
#define HIDDEN   5120
#define NEXP     160
#define NGROUP   8
#define EPG      20
#define TOPK     6
#define KCHUNK   64
#define NCHUNKS  80
#define NTILES   256              // 32768 / 128
#define NTHREADS 256
#define LO_SCALE 2048.0f
#define LO_INV   (1.0f / 2048.0f)

// ---------------- smem layout ----------------
#define SA_OFF(buf, hl) ((buf) * 32768 + (hl) * 16384)
#define SB_OFF(buf, hl) (65536 + (buf) * 40960 + (hl) * 20480)
#define SMEM_BYTES 188416
#define BTILE_BYTES 20480
#define RED_OFF 86016           // 2 x 128 floats
#define G8_OFF  87040           // 8 x 128 floats

#define SWZ(o) ((uint32_t)(o) ^ (((uint32_t)(o) >> 3) & 0x70))

// ---------------- device scratch ----------------
__device__ __align__(16) unsigned char g_whi[NCHUNKS * BTILE_BYTES];
__device__ __align__(16) unsigned char g_wlo[NCHUNKS * BTILE_BYTES];
__device__ __align__(16) float g_part[NTILES * 2 * 128 * NEXP];
__device__ int g_done[NTILES];

// ---------------- helpers ----------------
__device__ __forceinline__ uint32_t smem_u32(const void* p) {
    uint32_t a;
    asm("{ .reg .u64 t; cvta.to.shared.u64 t, %1; cvt.u32.u64 %0, t; }"
        : "=r"(a) : "l"(p));
    return a;
}
__device__ __forceinline__ uint32_t h2_bits(__half2 h) {
    return *reinterpret_cast<uint32_t*>(&h);
}
__device__ __forceinline__ int owner(int w) {
    return (w < 7784) ? (w / 139) : ((w - 56) / 138);
}

#define LDSM_X4(r0, r1, r2, r3, addr) \
    asm volatile("ldmatrix.sync.aligned.m8n8.x4.shared.b16 {%0,%1,%2,%3}, [%4];" \
                 : "=r"(r0), "=r"(r1), "=r"(r2), "=r"(r3) : "r"(addr))
#define MMA_F32(d, a0, a1, a2, a3, b0, b1) \
    asm("mma.sync.aligned.m16n8k16.row.col.f32.f16.f16.f32 " \
        "{%0,%1,%2,%3}, {%4,%5,%6,%7}, {%8,%9}, {%0,%1,%2,%3};" \
        : "+f"((d)[0]), "+f"((d)[1]), "+f"((d)[2]), "+f"((d)[3]) \
        : "r"(a0), "r"(a1), "r"(a2), "r"(a3), "r"(b0), "r"(b1))
#define MMA_F16(d, a0, a1, a2, a3, b0, b1) \
    asm("mma.sync.aligned.m16n8k16.row.col.f16.f16.f16.f16 " \
        "{%0,%1}, {%2,%3,%4,%5}, {%6,%7}, {%0,%1};" \
        : "+r"((d)[0]), "+r"((d)[1]) \
        : "r"(a0), "r"(a1), "r"(a2), "r"(a3), "r"(b0), "r"(b1))
#define CP_ASYNC16(saddr, gptr) \
    asm volatile("cp.async.cg.shared.global [%0], [%1], 16;" \
                 :: "r"(saddr), "l"(gptr))
#define CP_COMMIT() asm volatile("cp.async.commit_group;" ::: "memory")
#define CP_WAIT0()  asm volatile("cp.async.wait_group 0;" ::: "memory")
#define CP_WAIT1()  asm volatile("cp.async.wait_group 1;" ::: "memory")

// ---------------- prep: split W + zero done counters ------------------------
__global__ void prep_w_kernel(const float* __restrict__ w) {
    int idx = blockIdx.x * 256 + threadIdx.x;
    if (idx < NTILES) g_done[idx] = 0;
    if (idx >= NEXP * (HIDDEN / 8)) return;
    int n  = idx / (HIDDEN / 8);
    int k8 = idx - n * (HIDDEN / 8);
    int k  = k8 * 8;
    const float4* src = reinterpret_cast<const float4*>(w + (size_t)n * HIDDEN + k);
    float4 v0 = src[0], v1 = src[1];
    float f[8] = {v0.x, v0.y, v0.z, v0.w, v1.x, v1.y, v1.z, v1.w};

    uint32_t hh[4], ll[4];
#pragma unroll
    for (int i = 0; i < 4; ++i) {
        __half2 h = __floats2half2_rn(f[2 * i], f[2 * i + 1]);
        hh[i] = h2_bits(h);
        float2 hf = __half22float2(h);
        __half2 l = __floats2half2_rn((f[2 * i]     - hf.x) * LO_SCALE,
                                      (f[2 * i + 1] - hf.y) * LO_SCALE);
        ll[i] = h2_bits(l);
    }
    int c   = k >> 6;
    int col = k & 63;
    uint32_t sw = SWZ(n * 128 + col * 2);
    *reinterpret_cast<uint4*>(g_whi + (size_t)c * BTILE_BYTES + sw) =
        make_uint4(hh[0], hh[1], hh[2], hh[3]);
    *reinterpret_cast<uint4*>(g_wlo + (size_t)c * BTILE_BYTES + sw) =
        make_uint4(ll[0], ll[1], ll[2], ll[3]);
}

// ---------------- A convert + swizzled store helper -------------------------
__device__ __forceinline__ void cvt_store_a(char* smem, int bufA,
                                            const float4* xv, const uint32_t* sts_off,
                                            int it0, int it1) {
#pragma unroll
    for (int it = 0; it < 8; ++it) {
        if (it < it0 || it >= it1) continue;
        float4 v = xv[it];
        __half2 h01 = __floats2half2_rn(v.x, v.y);
        __half2 h23 = __floats2half2_rn(v.z, v.w);
        float2 f01 = __half22float2(h01);
        float2 f23 = __half22float2(h23);
        __half2 l01 = __floats2half2_rn((v.x - f01.x) * LO_SCALE, (v.y - f01.y) * LO_SCALE);
        __half2 l23 = __floats2half2_rn((v.z - f23.x) * LO_SCALE, (v.w - f23.y) * LO_SCALE);
        *reinterpret_cast<uint2*>(smem + SA_OFF(bufA, 0) + sts_off[it]) =
            make_uint2(h2_bits(h01), h2_bits(h23));
        *reinterpret_cast<uint2*>(smem + SA_OFF(bufA, 1) + sts_off[it]) =
            make_uint2(h2_bits(l01), h2_bits(l23));
    }
}

// ---------------- main fused kernel ----------------------------------------
__global__ __launch_bounds__(NTHREADS, 1)
void moe_gate_kernel(const float* __restrict__ x, float* __restrict__ out) {
    extern __shared__ __align__(1024) char smem[];
    __shared__ int flag_s;
    const uint32_t sb = smem_u32(smem);
    const int tid  = threadIdx.x;
    const int lane = tid & 31;
    const int wid  = tid >> 5;
    const int wm   = wid >> 2;
    const int wn   = wid & 3;
    const int swoff = wm * 2;

    const int g  = tid & 15;
    const int rg = tid >> 4;

    uint32_t sts_off[8];
#pragma unroll
    for (int it = 0; it < 8; ++it) {
        int row = rg + it * 16;
        sts_off[it] = (uint32_t)(row * 128) + (((uint32_t)(g * 8)) ^ ((uint32_t)(row & 7) << 4));
    }

    const int grp = lane >> 3;
    const int lr  = lane & 7;

    uint32_t a_row_off[4], a_swm[4];
#pragma unroll
    for (int mi = 0; mi < 4; ++mi) {
        int row = wm * 64 + mi * 16 + (grp & 1) * 8 + lr;
        a_row_off[mi] = (uint32_t)(row * 128);
        a_swm[mi]     = (uint32_t)(row & 7) << 4;
    }
    const int a_segadd = (grp >> 1);

    uint32_t b_row_off[2], b_swm[2];
#pragma unroll
    for (int p = 0; p < 2; ++p) {
        int n = wn * 40 + p * 16 + (grp >> 1) * 8 + lr;
        b_row_off[p] = (uint32_t)(n * 128);
        b_swm[p]     = (uint32_t)(n & 7) << 4;
    }
    const int b_segadd = (grp & 1);
    // merged tail: lanes 0-15 address the hi tile, lanes 16-31 the lo tile
    int n2 = wn * 40 + 32 + ((lane & 15) & 7);
    const uint32_t b2_row_off = (uint32_t)(n2 * 128);
    const uint32_t b2_swm     = (uint32_t)(n2 & 7) << 4;
    const int b2_segadd = ((lane & 15) >> 3);
    const int tail_hi   = (lane < 16);

    const int bid   = blockIdx.x;
    const int start = (bid < 56) ? 139 * bid : 138 * bid + 56;
    const int cnt   = (bid < 56) ? 139 : 138;
    const int wend  = start + cnt;

    int w = start;
    while (w < wend) {
        const int t  = w / NCHUNKS;
        const int c0 = w - NCHUNKS * t;
        const int c1 = min(wend - NCHUNKS * t, NCHUNKS);
        const int m0 = t * 128;
        const float* xbase = x + (size_t)(m0 + rg) * HIDDEN + g * 4;

        float    facc[4][5][4];
        uint32_t hacc[4][5][2];
#pragma unroll
        for (int mi = 0; mi < 4; ++mi)
#pragma unroll
            for (int nj = 0; nj < 5; ++nj) {
#pragma unroll
                for (int q = 0; q < 4; ++q) facc[mi][nj][q] = 0.f;
                hacc[mi][nj][0] = 0u; hacc[mi][nj][1] = 0u;
            }
        float4 xv[8];

        __syncthreads();    // smem free from previous segment / epilogue
        // ---------------- prologue: stage B(c0)[,B(c0+1)], A(c0) -----------
        {
#pragma unroll
            for (int i = 0; i < 5; ++i) {
                uint32_t o = (uint32_t)(i * 256 + tid) * 16;
                CP_ASYNC16(sb + SB_OFF(0, 0) + o, g_whi + (size_t)c0 * BTILE_BYTES + o);
                CP_ASYNC16(sb + SB_OFF(0, 1) + o, g_wlo + (size_t)c0 * BTILE_BYTES + o);
            }
            CP_COMMIT();
            const bool two = (c0 + 1 < c1);
            if (two) {
#pragma unroll
                for (int i = 0; i < 5; ++i) {
                    uint32_t o = (uint32_t)(i * 256 + tid) * 16;
                    CP_ASYNC16(sb + SB_OFF(1, 0) + o, g_whi + (size_t)(c0 + 1) * BTILE_BYTES + o);
                    CP_ASYNC16(sb + SB_OFF(1, 1) + o, g_wlo + (size_t)(c0 + 1) * BTILE_BYTES + o);
                }
                CP_COMMIT();
            }
#pragma unroll
            for (int it = 0; it < 8; ++it)
                xv[it] = *reinterpret_cast<const float4*>(
                    xbase + (size_t)c0 * KCHUNK + (size_t)(it * 16) * HIDDEN);
            cvt_store_a(smem, 0, xv, sts_off, 0, 8);
            if (two) CP_WAIT1(); else CP_WAIT0();
            __syncthreads();
        }

        // ---------------- segment main loop ----------------
        int bufB = 0, bufA = 0;
        for (int c = c0; c < c1; ++c) {
            const bool more = (c + 1 < c1);
            // issue B(c+2): safe — full barrier ended chunk c-1, its buffer is free
            if (c + 2 < c1) {
                int bw = bufB + 2; if (bw >= 3) bw -= 3;
                const size_t bo = (size_t)(c + 2) * BTILE_BYTES;
#pragma unroll
                for (int i = 0; i < 5; ++i) {
                    uint32_t o = (uint32_t)(i * 256 + tid) * 16;
                    CP_ASYNC16(sb + SB_OFF(bw, 0) + o, g_whi + bo + o);
                    CP_ASYNC16(sb + SB_OFF(bw, 1) + o, g_wlo + bo + o);
                }
                CP_COMMIT();
            }
            if (more) {
                const float* xc = xbase + (size_t)(c + 1) * KCHUNK;
#pragma unroll
                for (int it = 0; it < 8; ++it)
                    xv[it] = *reinterpret_cast<const float4*>(xc + (size_t)(it * 16) * HIDDEN);
            }

            const uint32_t aHi = sb + SA_OFF(bufA, 0);
            const uint32_t aLo = sb + SA_OFF(bufA, 1);
            const uint32_t bHi = sb + SB_OFF(bufB, 0);
            const uint32_t bLo = sb + SB_OFF(bufB, 1);

#pragma unroll
            for (int s = 0; s < 4; ++s) {
                const int sidx = (s + swoff) & 3;
                uint32_t bh[10], bl[10];
#pragma unroll
                for (int p = 0; p < 2; ++p) {
                    uint32_t seg = (uint32_t)(2 * sidx + b_segadd) << 4;
                    uint32_t off = b_row_off[p] + (seg ^ b_swm[p]);
                    LDSM_X4(bh[4 * p + 0], bh[4 * p + 1], bh[4 * p + 2], bh[4 * p + 3], bHi + off);
                    LDSM_X4(bl[4 * p + 0], bl[4 * p + 1], bl[4 * p + 2], bl[4 * p + 3], bLo + off);
                }
                {   // merged hi/lo tail (lanes 0-15: hi tile, 16-31: lo tile)
                    uint32_t seg = (uint32_t)(2 * sidx + b2_segadd) << 4;
                    uint32_t off = b2_row_off + (seg ^ b2_swm);
                    uint32_t base = tail_hi ? bHi : bLo;
                    LDSM_X4(bh[8], bh[9], bl[8], bl[9], base + off);
                }
#pragma unroll
                for (int mi = 0; mi < 4; ++mi) {
                    uint32_t seg = (uint32_t)(2 * sidx + a_segadd) << 4;
                    uint32_t off = a_row_off[mi] + (seg ^ a_swm[mi]);
                    uint32_t ah0, ah1, ah2, ah3, al0, al1, al2, al3;
                    LDSM_X4(ah0, ah1, ah2, ah3, aHi + off);
                    LDSM_X4(al0, al1, al2, al3, aLo + off);
#pragma unroll
                    for (int nj = 0; nj < 5; ++nj)
                        MMA_F32(facc[mi][nj], ah0, ah1, ah2, ah3, bh[2 * nj], bh[2 * nj + 1]);
#pragma unroll
                    for (int nj = 0; nj < 5; ++nj)
                        MMA_F16(hacc[mi][nj], ah0, ah1, ah2, ah3, bl[2 * nj], bl[2 * nj + 1]);
#pragma unroll
                    for (int nj = 0; nj < 5; ++nj)
                        MMA_F16(hacc[mi][nj], al0, al1, al2, al3, bh[2 * nj], bh[2 * nj + 1]);
                }
                if (s == 1 && more) cvt_store_a(smem, bufA ^ 1, xv, sts_off, 0, 4);
                if (s == 3 && more) cvt_store_a(smem, bufA ^ 1, xv, sts_off, 4, 8);
            }

            if (c + 2 < c1)      CP_WAIT1();
            else if (more)       CP_WAIT0();
            __syncthreads();
            bufA ^= 1;
            bufB += 1; if (bufB >= 3) bufB -= 3;
        }

        // ---------------- write partial logits to global slot ---------------
        const int b0own = owner(NCHUNKS * t);
        const int slot  = bid - b0own;
        float* gp = g_part + ((size_t)t * 2 + slot) * (128 * NEXP);
#pragma unroll
        for (int mi = 0; mi < 4; ++mi) {
            int r0 = wm * 64 + mi * 16 + (lane >> 2);
#pragma unroll
            for (int nj = 0; nj < 5; ++nj) {
                int cb = wn * 40 + nj * 8 + (lane & 3) * 2;
                float2 c0v = __half22float2(*reinterpret_cast<__half2*>(&hacc[mi][nj][0]));
                float2 c1v = __half22float2(*reinterpret_cast<__half2*>(&hacc[mi][nj][1]));
                *reinterpret_cast<float2*>(gp + (size_t)r0 * NEXP + cb) =
                    make_float2(facc[mi][nj][0] + c0v.x * LO_INV,
                                facc[mi][nj][1] + c0v.y * LO_INV);
                *reinterpret_cast<float2*>(gp + (size_t)(r0 + 8) * NEXP + cb) =
                    make_float2(facc[mi][nj][2] + c1v.x * LO_INV,
                                facc[mi][nj][3] + c1v.y * LO_INV);
            }
        }
        __threadfence();
        if (tid == 0) {
            int nctr = owner(NCHUNKS * t + NCHUNKS - 1) - b0own + 1;
            int old = atomicAdd(&g_done[t], 1);
            flag_s = (old == nctr - 1) ? nctr : 0;
        }
        __syncthreads();
        const int n_contrib = flag_s;

        // ---------------- epilogue (last finisher only) ----------------------
        if (n_contrib) {
            __threadfence();
            float* red = reinterpret_cast<float*>(smem + RED_OFF);
            float* g8  = reinterpret_cast<float*>(smem + G8_OFF);
            const int tok = tid & 127;
            const int seg = tid >> 7;
            const int e0  = seg * 80;
            const float* gp0 = g_part + (size_t)t * 2 * (128 * NEXP) + (size_t)tok * NEXP + e0;

            float z[80];
#pragma unroll
            for (int j = 0; j < 80; j += 2) {
                float2 v = __ldcg(reinterpret_cast<const float2*>(gp0 + j));
                if (n_contrib == 2) {
                    float2 v2 = __ldcg(reinterpret_cast<const float2*>(gp0 + 128 * NEXP + j));
                    v.x += v2.x; v.y += v2.y;
                }
                z[j] = v.x; z[j + 1] = v.y;
            }

            float mx = -3.4e38f;
#pragma unroll
            for (int j = 0; j < 80; ++j) mx = fmaxf(mx, z[j]);
            red[seg * 128 + tok] = mx;
            __syncthreads();
            mx = fmaxf(red[tok], red[128 + tok]);
            __syncthreads();

            float sum = 0.f;
#pragma unroll
            for (int j = 0; j < 80; ++j) {
                float p = __expf(z[j] - mx);
                sum += p;
                z[j] = p;
            }
            red[seg * 128 + tok] = sum;
            __syncthreads();
            sum = red[tok] + red[128 + tok];

            float gm[4];
#pragma unroll
            for (int q = 0; q < 4; ++q) {
                float m = 0.f;
#pragma unroll
                for (int tt = 0; tt < EPG; ++tt) m = fmaxf(m, z[q * EPG + tt]);
                gm[q] = m;
                g8[(seg * 4 + q) * 128 + tok] = m;
            }
            __syncthreads();

            float gv[NGROUP];
#pragma unroll
            for (int q = 0; q < NGROUP; ++q) gv[q] = g8[q * 128 + tok];
            float t1 = 0.f, t2 = 0.f, t3 = 0.f;
#pragma unroll
            for (int q = 0; q < NGROUP; ++q) t1 = fmaxf(t1, gv[q]);
#pragma unroll
            for (int q = 0; q < NGROUP; ++q) t2 = fmaxf(t2, (gv[q] < t1) ? gv[q] : 0.f);
#pragma unroll
            for (int q = 0; q < NGROUP; ++q) t3 = fmaxf(t3, (gv[q] < t2) ? gv[q] : 0.f);

#pragma unroll
            for (int q = 0; q < 4; ++q) {
                float keep = (gm[q] >= t3) ? 1.f : 0.f;
#pragma unroll
                for (int tt = 0; tt < EPG; ++tt) z[q * EPG + tt] *= keep;
            }

            const float inv = 16.0f / sum;
            float* orow = out + (size_t)(m0 + tok) * TOPK;
            float prev = 3.4e38f;
            __syncthreads();
            for (int i = 0; i < TOPK; ++i) {
                float cand = 0.f;
#pragma unroll
                for (int j = 0; j < 80; ++j)
                    cand = fmaxf(cand, (z[j] < prev) ? z[j] : 0.f);
                red[seg * 128 + tok] = cand;
                __syncthreads();
                float cur = fmaxf(red[tok], red[128 + tok]);
                __syncthreads();
                if (seg == 0) orow[i] = cur * inv;
                prev = cur;
            }
        }

        w = NCHUNKS * t + c1;
    }
}

// ---------------- launch ----------------------------------------------------
extern "C" void kernel_launch(void* const* d_in, const int* in_sizes, int n_in,
                              void* d_out, int out_size) {
    const float* x = (const float*)d_in[0];   // [32768, 5120] fp32
    const float* w = (const float*)d_in[1];   // [160, 5120] fp32
    float* out = (float*)d_out;               // [32768, 6] fp32

    cudaFuncSetAttribute(moe_gate_kernel,
                         cudaFuncAttributeMaxDynamicSharedMemorySize, SMEM_BYTES);

    int prep_elems = NEXP * (HIDDEN / 8);
    prep_w_kernel<<<(prep_elems + 255) / 256, 256>>>(w);
    moe_gate_kernel<<<148, NTHREADS, SMEM_BYTES>>>(x, out);
}

// round 16
// speedup vs baseline: 1.0432x; 1.0397x over previous
#include <cuda_runtime.h>
#include <cuda_fp16.h>
#include <cstdint>

// ---------------- problem constants ----------------
#define TOKENS   32768
#define HIDDEN   5120
#define NEXP     160
#define NGROUP   8
#define EPG      20
#define TOPK     6
#define KCHUNK   64
#define NCHUNKS  80
#define NTILES   256              // 32768 / 128
#define NTHREADS 256
#define LO_SCALE 2048.0f
#define LO_INV   (1.0f / 2048.0f)

// ---------------- smem layout (same as R8) ----------------
#define SA_OFF(buf, hl) ((buf) * 32768 + (hl) * 16384)
#define SB_OFF(buf, hl) (65536 + (buf) * 40960 + (hl) * 20480)
#define SMEM_BYTES 188416
#define BTILE_BYTES 20480
#define RED_OFF 86016           // 2 x 128 floats (overlays B, used only in epilogue)
#define G8_OFF  87040           // 8 x 128 floats

#define SWZ(o) ((uint32_t)(o) ^ (((uint32_t)(o) >> 3) & 0x70))

// ---------------- device scratch ----------------
__device__ __align__(16) unsigned char g_whi[NCHUNKS * BTILE_BYTES];
__device__ __align__(16) unsigned char g_wlo[NCHUNKS * BTILE_BYTES];
__device__ __align__(16) float g_part[NTILES * 2 * 128 * NEXP];   // [tile][slot][128][160]
__device__ int g_done[NTILES];

// ---------------- helpers ----------------
__device__ __forceinline__ uint32_t smem_u32(const void* p) {
    uint32_t a;
    asm("{ .reg .u64 t; cvta.to.shared.u64 t, %1; cvt.u32.u64 %0, t; }"
        : "=r"(a) : "l"(p));
    return a;
}
__device__ __forceinline__ uint32_t h2_bits(__half2 h) {
    return *reinterpret_cast<uint32_t*>(&h);
}
// chunk-unit w -> owning CTA (56 CTAs x 139 + 92 CTAs x 138 = 20480)
__device__ __forceinline__ int owner(int w) {
    return (w < 7784) ? (w / 139) : ((w - 56) / 138);
}

#define LDSM_X4(r0, r1, r2, r3, addr) \
    asm volatile("ldmatrix.sync.aligned.m8n8.x4.shared.b16 {%0,%1,%2,%3}, [%4];" \
                 : "=r"(r0), "=r"(r1), "=r"(r2), "=r"(r3) : "r"(addr))
#define LDSM_X2(r0, r1, addr) \
    asm volatile("ldmatrix.sync.aligned.m8n8.x2.shared.b16 {%0,%1}, [%2];" \
                 : "=r"(r0), "=r"(r1) : "r"(addr))
#define MMA_F32(d, a0, a1, a2, a3, b0, b1) \
    asm("mma.sync.aligned.m16n8k16.row.col.f32.f16.f16.f32 " \
        "{%0,%1,%2,%3}, {%4,%5,%6,%7}, {%8,%9}, {%0,%1,%2,%3};" \
        : "+f"((d)[0]), "+f"((d)[1]), "+f"((d)[2]), "+f"((d)[3]) \
        : "r"(a0), "r"(a1), "r"(a2), "r"(a3), "r"(b0), "r"(b1))
#define MMA_F16(d, a0, a1, a2, a3, b0, b1) \
    asm("mma.sync.aligned.m16n8k16.row.col.f16.f16.f16.f16 " \
        "{%0,%1}, {%2,%3,%4,%5}, {%6,%7}, {%0,%1};" \
        : "+r"((d)[0]), "+r"((d)[1]) \
        : "r"(a0), "r"(a1), "r"(a2), "r"(a3), "r"(b0), "r"(b1))
#define CP_ASYNC16(saddr, gptr) \
    asm volatile("cp.async.cg.shared.global [%0], [%1], 16;" \
                 :: "r"(saddr), "l"(gptr))
#define CP_COMMIT() asm volatile("cp.async.commit_group;" ::: "memory")
#define CP_WAIT0()  asm volatile("cp.async.wait_group 0;" ::: "memory")
#define CP_WAIT1()  asm volatile("cp.async.wait_group 1;" ::: "memory")

// ---------------- prep: split W + zero done counters ------------------------
__global__ void prep_w_kernel(const float* __restrict__ w) {
    int idx = blockIdx.x * 256 + threadIdx.x;
    if (idx < NTILES) g_done[idx] = 0;
    if (idx >= NEXP * (HIDDEN / 8)) return;
    int n  = idx / (HIDDEN / 8);
    int k8 = idx - n * (HIDDEN / 8);
    int k  = k8 * 8;
    const float4* src = reinterpret_cast<const float4*>(w + (size_t)n * HIDDEN + k);
    float4 v0 = src[0], v1 = src[1];
    float f[8] = {v0.x, v0.y, v0.z, v0.w, v1.x, v1.y, v1.z, v1.w};

    uint32_t hh[4], ll[4];
#pragma unroll
    for (int i = 0; i < 4; ++i) {
        __half2 h = __floats2half2_rn(f[2 * i], f[2 * i + 1]);
        hh[i] = h2_bits(h);
        float2 hf = __half22float2(h);
        __half2 l = __floats2half2_rn((f[2 * i]     - hf.x) * LO_SCALE,
                                      (f[2 * i + 1] - hf.y) * LO_SCALE);
        ll[i] = h2_bits(l);
    }
    int c   = k >> 6;
    int col = k & 63;
    uint32_t sw = SWZ(n * 128 + col * 2);
    *reinterpret_cast<uint4*>(g_whi + (size_t)c * BTILE_BYTES + sw) =
        make_uint4(hh[0], hh[1], hh[2], hh[3]);
    *reinterpret_cast<uint4*>(g_wlo + (size_t)c * BTILE_BYTES + sw) =
        make_uint4(ll[0], ll[1], ll[2], ll[3]);
}

// ---------------- A convert + swizzled store helper -------------------------
__device__ __forceinline__ void cvt_store_a(char* smem, int bufA,
                                            const float4* xv, const uint32_t* sts_off,
                                            int it0, int it1) {
#pragma unroll
    for (int it = 0; it < 8; ++it) {
        if (it < it0 || it >= it1) continue;
        float4 v = xv[it];
        __half2 h01 = __floats2half2_rn(v.x, v.y);
        __half2 h23 = __floats2half2_rn(v.z, v.w);
        float2 f01 = __half22float2(h01);
        float2 f23 = __half22float2(h23);
        __half2 l01 = __floats2half2_rn((v.x - f01.x) * LO_SCALE, (v.y - f01.y) * LO_SCALE);
        __half2 l23 = __floats2half2_rn((v.z - f23.x) * LO_SCALE, (v.w - f23.y) * LO_SCALE);
        *reinterpret_cast<uint2*>(smem + SA_OFF(bufA, 0) + sts_off[it]) =
            make_uint2(h2_bits(h01), h2_bits(h23));
        *reinterpret_cast<uint2*>(smem + SA_OFF(bufA, 1) + sts_off[it]) =
            make_uint2(h2_bits(l01), h2_bits(l23));
    }
}

// ---------------- main fused kernel ----------------------------------------
__global__ __launch_bounds__(NTHREADS, 1)
void moe_gate_kernel(const float* __restrict__ x, float* __restrict__ out) {
    extern __shared__ __align__(1024) char smem[];
    __shared__ int flag_s;
    const uint32_t sb = smem_u32(smem);
    const int tid  = threadIdx.x;
    const int lane = tid & 31;
    const int wid  = tid >> 5;
    const int wm   = wid >> 2;
    const int wn   = wid & 3;
    const int swoff = wm * 2;

    const int g  = tid & 15;
    const int rg = tid >> 4;

    uint32_t sts_off[8];
#pragma unroll
    for (int it = 0; it < 8; ++it) {
        int row = rg + it * 16;
        sts_off[it] = (uint32_t)(row * 128) + (((uint32_t)(g * 8)) ^ ((uint32_t)(row & 7) << 4));
    }

    const int grp = lane >> 3;
    const int lr  = lane & 7;

    uint32_t a_row_off[4], a_swm[4];
#pragma unroll
    for (int mi = 0; mi < 4; ++mi) {
        int row = wm * 64 + mi * 16 + (grp & 1) * 8 + lr;
        a_row_off[mi] = (uint32_t)(row * 128);
        a_swm[mi]     = (uint32_t)(row & 7) << 4;
    }
    const int a_segadd = (grp >> 1);

    uint32_t b_row_off[2], b_swm[2];
#pragma unroll
    for (int p = 0; p < 2; ++p) {
        int n = wn * 40 + p * 16 + (grp >> 1) * 8 + lr;
        b_row_off[p] = (uint32_t)(n * 128);
        b_swm[p]     = (uint32_t)(n & 7) << 4;
    }
    const int b_segadd = (grp & 1);
    int n2 = wn * 40 + 32 + ((lane & 15) & 7);
    const uint32_t b2_row_off = (uint32_t)(n2 * 128);
    const uint32_t b2_swm     = (uint32_t)(n2 & 7) << 4;
    const int b2_segadd = ((lane & 15) >> 3);

    const int bid   = blockIdx.x;
    const int start = (bid < 56) ? 139 * bid : 138 * bid + 56;
    const int cnt   = (bid < 56) ? 139 : 138;
    const int wend  = start + cnt;

    int w = start;
    while (w < wend) {
        const int t  = w / NCHUNKS;
        const int c0 = w - NCHUNKS * t;
        const int c1 = min(wend - NCHUNKS * t, NCHUNKS);
        const int m0 = t * 128;
        const float* xbase = x + (size_t)(m0 + rg) * HIDDEN + g * 4;

        float    facc[4][5][4];
        uint32_t hacc[4][5][2];
#pragma unroll
        for (int mi = 0; mi < 4; ++mi)
#pragma unroll
            for (int nj = 0; nj < 5; ++nj) {
#pragma unroll
                for (int q = 0; q < 4; ++q) facc[mi][nj][q] = 0.f;
                hacc[mi][nj][0] = 0u; hacc[mi][nj][1] = 0u;
            }
        float4 xv[8];

        __syncthreads();    // smem free from previous segment / epilogue
        // ---------------- prologue: stage B(c0)[,B(c0+1)], A(c0) -----------
        {
#pragma unroll
            for (int i = 0; i < 5; ++i) {
                uint32_t o = (uint32_t)(i * 256 + tid) * 16;
                CP_ASYNC16(sb + SB_OFF(0, 0) + o, g_whi + (size_t)c0 * BTILE_BYTES + o);
                CP_ASYNC16(sb + SB_OFF(0, 1) + o, g_wlo + (size_t)c0 * BTILE_BYTES + o);
            }
            CP_COMMIT();
            const bool two = (c0 + 1 < c1);
            if (two) {
#pragma unroll
                for (int i = 0; i < 5; ++i) {
                    uint32_t o = (uint32_t)(i * 256 + tid) * 16;
                    CP_ASYNC16(sb + SB_OFF(1, 0) + o, g_whi + (size_t)(c0 + 1) * BTILE_BYTES + o);
                    CP_ASYNC16(sb + SB_OFF(1, 1) + o, g_wlo + (size_t)(c0 + 1) * BTILE_BYTES + o);
                }
                CP_COMMIT();
            }
#pragma unroll
            for (int it = 0; it < 8; ++it)
                xv[it] = *reinterpret_cast<const float4*>(xbase + (size_t)c0 * KCHUNK + (size_t)(it * 16) * HIDDEN);
            cvt_store_a(smem, 0, xv, sts_off, 0, 8);
            if (two) CP_WAIT1(); else CP_WAIT0();
            __syncthreads();
        }

        // ---------------- segment main loop ----------------
        int bufB = 0, bufA = 0;
        for (int c = c0; c < c1; ++c) {
            const bool more = (c + 1 < c1);
            if (c + 2 < c1) {
                int bw = bufB + 2; if (bw >= 3) bw -= 3;
                const size_t bo = (size_t)(c + 2) * BTILE_BYTES;
#pragma unroll
                for (int i = 0; i < 5; ++i) {
                    uint32_t o = (uint32_t)(i * 256 + tid) * 16;
                    CP_ASYNC16(sb + SB_OFF(bw, 0) + o, g_whi + bo + o);
                    CP_ASYNC16(sb + SB_OFF(bw, 1) + o, g_wlo + bo + o);
                }
                CP_COMMIT();
            }
            if (more) {
                const float* xc = xbase + (size_t)(c + 1) * KCHUNK;
#pragma unroll
                for (int it = 0; it < 8; ++it)
                    xv[it] = *reinterpret_cast<const float4*>(xc + (size_t)(it * 16) * HIDDEN);
            }

            const uint32_t aHi = sb + SA_OFF(bufA, 0);
            const uint32_t aLo = sb + SA_OFF(bufA, 1);
            const uint32_t bHi = sb + SB_OFF(bufB, 0);
            const uint32_t bLo = sb + SB_OFF(bufB, 1);

#pragma unroll
            for (int s = 0; s < 4; ++s) {
                const int sidx = (s + swoff) & 3;
                uint32_t bh[10], bl[10];
#pragma unroll
                for (int p = 0; p < 2; ++p) {
                    uint32_t seg = (uint32_t)(2 * sidx + b_segadd) << 4;
                    uint32_t off = b_row_off[p] + (seg ^ b_swm[p]);
                    LDSM_X4(bh[4 * p + 0], bh[4 * p + 1], bh[4 * p + 2], bh[4 * p + 3], bHi + off);
                    LDSM_X4(bl[4 * p + 0], bl[4 * p + 1], bl[4 * p + 2], bl[4 * p + 3], bLo + off);
                }
                {
                    uint32_t seg = (uint32_t)(2 * sidx + b2_segadd) << 4;
                    uint32_t off = b2_row_off + (seg ^ b2_swm);
                    LDSM_X2(bh[8], bh[9], bHi + off);
                    LDSM_X2(bl[8], bl[9], bLo + off);
                }
#pragma unroll
                for (int mi = 0; mi < 4; ++mi) {
                    uint32_t seg = (uint32_t)(2 * sidx + a_segadd) << 4;
                    uint32_t off = a_row_off[mi] + (seg ^ a_swm[mi]);
                    uint32_t ah0, ah1, ah2, ah3, al0, al1, al2, al3;
                    LDSM_X4(ah0, ah1, ah2, ah3, aHi + off);
                    LDSM_X4(al0, al1, al2, al3, aLo + off);
#pragma unroll
                    for (int nj = 0; nj < 5; ++nj)
                        MMA_F32(facc[mi][nj], ah0, ah1, ah2, ah3, bh[2 * nj], bh[2 * nj + 1]);
#pragma unroll
                    for (int nj = 0; nj < 5; ++nj)
                        MMA_F16(hacc[mi][nj], ah0, ah1, ah2, ah3, bl[2 * nj], bl[2 * nj + 1]);
#pragma unroll
                    for (int nj = 0; nj < 5; ++nj)
                        MMA_F16(hacc[mi][nj], al0, al1, al2, al3, bh[2 * nj], bh[2 * nj + 1]);
                }
                if (s == 1 && more) cvt_store_a(smem, bufA ^ 1, xv, sts_off, 0, 4);
                if (s == 3 && more) cvt_store_a(smem, bufA ^ 1, xv, sts_off, 4, 8);
            }

            if (c + 2 < c1)      CP_WAIT1();
            else if (c + 1 < c1) CP_WAIT0();
            __syncthreads();
            bufA ^= 1;
            bufB += 1; if (bufB >= 3) bufB -= 3;
        }

        // ---------------- write partial logits to global slot ---------------
        const int b0own = owner(NCHUNKS * t);
        const int slot  = bid - b0own;
        float* gp = g_part + ((size_t)t * 2 + slot) * (128 * NEXP);
#pragma unroll
        for (int mi = 0; mi < 4; ++mi) {
            int r0 = wm * 64 + mi * 16 + (lane >> 2);
#pragma unroll
            for (int nj = 0; nj < 5; ++nj) {
                int cb = wn * 40 + nj * 8 + (lane & 3) * 2;
                float2 c0v = __half22float2(*reinterpret_cast<__half2*>(&hacc[mi][nj][0]));
                float2 c1v = __half22float2(*reinterpret_cast<__half2*>(&hacc[mi][nj][1]));
                *reinterpret_cast<float2*>(gp + (size_t)r0 * NEXP + cb) =
                    make_float2(facc[mi][nj][0] + c0v.x * LO_INV,
                                facc[mi][nj][1] + c0v.y * LO_INV);
                *reinterpret_cast<float2*>(gp + (size_t)(r0 + 8) * NEXP + cb) =
                    make_float2(facc[mi][nj][2] + c1v.x * LO_INV,
                                facc[mi][nj][3] + c1v.y * LO_INV);
            }
        }
        __threadfence();
        if (tid == 0) {
            int nctr = owner(NCHUNKS * t + NCHUNKS - 1) - b0own + 1;
            int old = atomicAdd(&g_done[t], 1);
            flag_s = (old == nctr - 1) ? nctr : 0;
        }
        __syncthreads();
        const int n_contrib = flag_s;

        // ---------------- epilogue (last finisher only) ----------------------
        if (n_contrib) {
            __threadfence();
            float* red = reinterpret_cast<float*>(smem + RED_OFF);
            float* g8  = reinterpret_cast<float*>(smem + G8_OFF);
            const int tok = tid & 127;
            const int seg = tid >> 7;
            const int e0  = seg * 80;
            const float* gp0 = g_part + (size_t)t * 2 * (128 * NEXP) + (size_t)tok * NEXP + e0;

            float z[80];
#pragma unroll
            for (int j = 0; j < 80; j += 2) {
                float2 v = __ldcg(reinterpret_cast<const float2*>(gp0 + j));
                if (n_contrib == 2) {
                    float2 v2 = __ldcg(reinterpret_cast<const float2*>(gp0 + 128 * NEXP + j));
                    v.x += v2.x; v.y += v2.y;
                }
                z[j] = v.x; z[j + 1] = v.y;
            }

            float mx = -3.4e38f;
#pragma unroll
            for (int j = 0; j < 80; ++j) mx = fmaxf(mx, z[j]);
            red[seg * 128 + tok] = mx;
            __syncthreads();
            mx = fmaxf(red[tok], red[128 + tok]);
            __syncthreads();

            float sum = 0.f;
#pragma unroll
            for (int j = 0; j < 80; ++j) {
                float p = __expf(z[j] - mx);
                sum += p;
                z[j] = p;
            }
            red[seg * 128 + tok] = sum;
            __syncthreads();
            sum = red[tok] + red[128 + tok];

            float gm[4];
#pragma unroll
            for (int q = 0; q < 4; ++q) {
                float m = 0.f;
#pragma unroll
                for (int tt = 0; tt < EPG; ++tt) m = fmaxf(m, z[q * EPG + tt]);
                gm[q] = m;
                g8[(seg * 4 + q) * 128 + tok] = m;
            }
            __syncthreads();

            float gv[NGROUP];
#pragma unroll
            for (int q = 0; q < NGROUP; ++q) gv[q] = g8[q * 128 + tok];
            float t1 = 0.f, t2 = 0.f, t3 = 0.f;
#pragma unroll
            for (int q = 0; q < NGROUP; ++q) t1 = fmaxf(t1, gv[q]);
#pragma unroll
            for (int q = 0; q < NGROUP; ++q) t2 = fmaxf(t2, (gv[q] < t1) ? gv[q] : 0.f);
#pragma unroll
            for (int q = 0; q < NGROUP; ++q) t3 = fmaxf(t3, (gv[q] < t2) ? gv[q] : 0.f);

#pragma unroll
            for (int q = 0; q < 4; ++q) {
                float keep = (gm[q] >= t3) ? 1.f : 0.f;
#pragma unroll
                for (int tt = 0; tt < EPG; ++tt) z[q * EPG + tt] *= keep;
            }

            const float inv = 16.0f / sum;
            float* orow = out + (size_t)(m0 + tok) * TOPK;
            float prev = 3.4e38f;
            __syncthreads();
            for (int i = 0; i < TOPK; ++i) {
                float cand = 0.f;
#pragma unroll
                for (int j = 0; j < 80; ++j)
                    cand = fmaxf(cand, (z[j] < prev) ? z[j] : 0.f);
                red[seg * 128 + tok] = cand;
                __syncthreads();
                float cur = fmaxf(red[tok], red[128 + tok]);
                __syncthreads();
                if (seg == 0) orow[i] = cur * inv;
                prev = cur;
            }
        }

        w = NCHUNKS * t + c1;
    }
}

// ---------------- launch ----------------------------------------------------
extern "C" void kernel_launch(void* const* d_in, const int* in_sizes, int n_in,
                              void* d_out, int out_size) {
    const float* x = (const float*)d_in[0];   // [32768, 5120] fp32
    const float* w = (const float*)d_in[1];   // [160, 5120] fp32
    float* out = (float*)d_out;               // [32768, 6] fp32

    cudaFuncSetAttribute(moe_gate_kernel,
                         cudaFuncAttributeMaxDynamicSharedMemorySize, SMEM_BYTES);

    int prep_elems = NEXP * (HIDDEN / 8);
    prep_w_kernel<<<(prep_elems + 255) / 256, 256>>>(w);
    moe_gate_kernel<<<148, NTHREADS, SMEM_BYTES>>>(x, out);
}

// round 17
// speedup vs baseline: 1.0433x; 1.0001x over previous
#include <cuda_runtime.h>
#include <cuda_fp16.h>
#include <cstdint>

// ---------------- problem constants ----------------
#define TOKENS   32768
#define HIDDEN   5120
#define NEXP     160
#define NGROUP   8
#define EPG      20
#define TOPK     6
#define KCHUNK   64
#define NCHUNKS  80
#define NTILES   256              // 32768 / 128
#define NTHREADS 256
#define LO_SCALE 2048.0f
#define LO_INV   (1.0f / 2048.0f)

// ---------------- smem layout ----------------
#define SA_OFF(buf, hl) ((buf) * 32768 + (hl) * 16384)
#define SB_OFF(buf, hl) (65536 + (buf) * 40960 + (hl) * 20480)
#define SMEM_BYTES 188416
#define BTILE_BYTES 20480
#define RED_OFF 86016           // 2 x 128 floats (overlays B, used only in epilogue)
#define G8_OFF  87040           // 8 x 128 floats

#define SWZ(o) ((uint32_t)(o) ^ (((uint32_t)(o) >> 3) & 0x70))

// ---------------- device scratch ----------------
__device__ __align__(16) unsigned char g_whi[NCHUNKS * BTILE_BYTES];
__device__ __align__(16) unsigned char g_wlo[NCHUNKS * BTILE_BYTES];
__device__ __align__(16) float g_part[NTILES * 2 * 128 * NEXP];   // [tile][slot][128][160]
__device__ int g_done[NTILES];

// ---------------- helpers ----------------
__device__ __forceinline__ uint32_t smem_u32(const void* p) {
    uint32_t a;
    asm("{ .reg .u64 t; cvta.to.shared.u64 t, %1; cvt.u32.u64 %0, t; }"
        : "=r"(a) : "l"(p));
    return a;
}
__device__ __forceinline__ uint32_t h2_bits(__half2 h) {
    return *reinterpret_cast<uint32_t*>(&h);
}
// chunk-unit w -> owning CTA (56 CTAs x 139 + 92 CTAs x 138 = 20480)
__device__ __forceinline__ int owner(int w) {
    return (w < 7784) ? (w / 139) : ((w - 56) / 138);
}

#define LDSM_X4(r0, r1, r2, r3, addr) \
    asm volatile("ldmatrix.sync.aligned.m8n8.x4.shared.b16 {%0,%1,%2,%3}, [%4];" \
                 : "=r"(r0), "=r"(r1), "=r"(r2), "=r"(r3) : "r"(addr))
#define LDSM_X2(r0, r1, addr) \
    asm volatile("ldmatrix.sync.aligned.m8n8.x2.shared.b16 {%0,%1}, [%2];" \
                 : "=r"(r0), "=r"(r1) : "r"(addr))
#define MMA_F32(d, a0, a1, a2, a3, b0, b1) \
    asm("mma.sync.aligned.m16n8k16.row.col.f32.f16.f16.f32 " \
        "{%0,%1,%2,%3}, {%4,%5,%6,%7}, {%8,%9}, {%0,%1,%2,%3};" \
        : "+f"((d)[0]), "+f"((d)[1]), "+f"((d)[2]), "+f"((d)[3]) \
        : "r"(a0), "r"(a1), "r"(a2), "r"(a3), "r"(b0), "r"(b1))
#define MMA_F16(d, a0, a1, a2, a3, b0, b1) \
    asm("mma.sync.aligned.m16n8k16.row.col.f16.f16.f16.f16 " \
        "{%0,%1}, {%2,%3,%4,%5}, {%6,%7}, {%0,%1};" \
        : "+r"((d)[0]), "+r"((d)[1]) \
        : "r"(a0), "r"(a1), "r"(a2), "r"(a3), "r"(b0), "r"(b1))
#define CP_ASYNC16(saddr, gptr) \
    asm volatile("cp.async.cg.shared.global [%0], [%1], 16;" \
                 :: "r"(saddr), "l"(gptr))
#define CP_COMMIT() asm volatile("cp.async.commit_group;" ::: "memory")
#define CP_WAIT0()  asm volatile("cp.async.wait_group 0;" ::: "memory")
#define CP_WAIT1()  asm volatile("cp.async.wait_group 1;" ::: "memory")

// ---------------- prep: split W + zero done counters ------------------------
__global__ void prep_w_kernel(const float* __restrict__ w) {
    int idx = blockIdx.x * 256 + threadIdx.x;
    if (idx < NTILES) g_done[idx] = 0;
    if (idx >= NEXP * (HIDDEN / 8)) return;
    int n  = idx / (HIDDEN / 8);
    int k8 = idx - n * (HIDDEN / 8);
    int k  = k8 * 8;
    const float4* src = reinterpret_cast<const float4*>(w + (size_t)n * HIDDEN + k);
    float4 v0 = src[0], v1 = src[1];
    float f[8] = {v0.x, v0.y, v0.z, v0.w, v1.x, v1.y, v1.z, v1.w};

    uint32_t hh[4], ll[4];
#pragma unroll
    for (int i = 0; i < 4; ++i) {
        __half2 h = __floats2half2_rn(f[2 * i], f[2 * i + 1]);
        hh[i] = h2_bits(h);
        float2 hf = __half22float2(h);
        __half2 l = __floats2half2_rn((f[2 * i]     - hf.x) * LO_SCALE,
                                      (f[2 * i + 1] - hf.y) * LO_SCALE);
        ll[i] = h2_bits(l);
    }
    int c   = k >> 6;
    int col = k & 63;
    uint32_t sw = SWZ(n * 128 + col * 2);
    *reinterpret_cast<uint4*>(g_whi + (size_t)c * BTILE_BYTES + sw) =
        make_uint4(hh[0], hh[1], hh[2], hh[3]);
    *reinterpret_cast<uint4*>(g_wlo + (size_t)c * BTILE_BYTES + sw) =
        make_uint4(ll[0], ll[1], ll[2], ll[3]);
}

// ---------------- A convert + swizzled store helper -------------------------
__device__ __forceinline__ void cvt_store_a(char* smem, int bufA,
                                            const float4* xv, const uint32_t* sts_off,
                                            int it0, int it1) {
#pragma unroll
    for (int it = 0; it < 8; ++it) {
        if (it < it0 || it >= it1) continue;
        float4 v = xv[it];
        __half2 h01 = __floats2half2_rn(v.x, v.y);
        __half2 h23 = __floats2half2_rn(v.z, v.w);
        float2 f01 = __half22float2(h01);
        float2 f23 = __half22float2(h23);
        __half2 l01 = __floats2half2_rn((v.x - f01.x) * LO_SCALE, (v.y - f01.y) * LO_SCALE);
        __half2 l23 = __floats2half2_rn((v.z - f23.x) * LO_SCALE, (v.w - f23.y) * LO_SCALE);
        *reinterpret_cast<uint2*>(smem + SA_OFF(bufA, 0) + sts_off[it]) =
            make_uint2(h2_bits(h01), h2_bits(h23));
        *reinterpret_cast<uint2*>(smem + SA_OFF(bufA, 1) + sts_off[it]) =
            make_uint2(h2_bits(l01), h2_bits(l23));
    }
}

// ---------------- main fused kernel ----------------------------------------
__global__ __launch_bounds__(NTHREADS, 1)
void moe_gate_kernel(const float* __restrict__ x, float* __restrict__ out) {
    extern __shared__ __align__(1024) char smem[];
    __shared__ int flag_s;
    const uint32_t sb = smem_u32(smem);
    const int tid  = threadIdx.x;
    const int lane = tid & 31;
    const int wid  = tid >> 5;
    const int wm   = wid >> 2;
    const int wn   = wid & 3;
    const int swoff = wm * 2;

    const int g  = tid & 15;
    const int rg = tid >> 4;

    uint32_t sts_off[8];
#pragma unroll
    for (int it = 0; it < 8; ++it) {
        int row = rg + it * 16;
        sts_off[it] = (uint32_t)(row * 128) + (((uint32_t)(g * 8)) ^ ((uint32_t)(row & 7) << 4));
    }

    const int grp = lane >> 3;
    const int lr  = lane & 7;

    uint32_t a_row_off[4], a_swm[4];
#pragma unroll
    for (int mi = 0; mi < 4; ++mi) {
        int row = wm * 64 + mi * 16 + (grp & 1) * 8 + lr;
        a_row_off[mi] = (uint32_t)(row * 128);
        a_swm[mi]     = (uint32_t)(row & 7) << 4;
    }
    const int a_segadd = (grp >> 1);

    uint32_t b_row_off[2], b_swm[2];
#pragma unroll
    for (int p = 0; p < 2; ++p) {
        int n = wn * 40 + p * 16 + (grp >> 1) * 8 + lr;
        b_row_off[p] = (uint32_t)(n * 128);
        b_swm[p]     = (uint32_t)(n & 7) << 4;
    }
    const int b_segadd = (grp & 1);
    int n2 = wn * 40 + 32 + ((lane & 15) & 7);
    const uint32_t b2_row_off = (uint32_t)(n2 * 128);
    const uint32_t b2_swm     = (uint32_t)(n2 & 7) << 4;
    const int b2_segadd = ((lane & 15) >> 3);

    const int bid   = blockIdx.x;
    const int start = (bid < 56) ? 139 * bid : 138 * bid + 56;
    const int cnt   = (bid < 56) ? 139 : 138;
    const int wend  = start + cnt;

    int w = start;
    while (w < wend) {
        const int t  = w / NCHUNKS;
        const int c0 = w - NCHUNKS * t;
        const int c1 = min(wend - NCHUNKS * t, NCHUNKS);
        const int m0 = t * 128;
        const float* xbase = x + (size_t)(m0 + rg) * HIDDEN + g * 4;

        float    facc[4][5][4];
        uint32_t hacc[4][5][2];
#pragma unroll
        for (int mi = 0; mi < 4; ++mi)
#pragma unroll
            for (int nj = 0; nj < 5; ++nj) {
#pragma unroll
                for (int q = 0; q < 4; ++q) facc[mi][nj][q] = 0.f;
                hacc[mi][nj][0] = 0u; hacc[mi][nj][1] = 0u;
            }
        float4 xv[8];

        __syncthreads();    // smem free from previous segment / epilogue
        // ---------------- prologue: stage B(c0)[,B(c0+1)], A(c0) -----------
        {
#pragma unroll
            for (int i = 0; i < 5; ++i) {
                uint32_t o = (uint32_t)(i * 256 + tid) * 16;
                CP_ASYNC16(sb + SB_OFF(0, 0) + o, g_whi + (size_t)c0 * BTILE_BYTES + o);
                CP_ASYNC16(sb + SB_OFF(0, 1) + o, g_wlo + (size_t)c0 * BTILE_BYTES + o);
            }
            CP_COMMIT();
            const bool two = (c0 + 1 < c1);
            if (two) {
#pragma unroll
                for (int i = 0; i < 5; ++i) {
                    uint32_t o = (uint32_t)(i * 256 + tid) * 16;
                    CP_ASYNC16(sb + SB_OFF(1, 0) + o, g_whi + (size_t)(c0 + 1) * BTILE_BYTES + o);
                    CP_ASYNC16(sb + SB_OFF(1, 1) + o, g_wlo + (size_t)(c0 + 1) * BTILE_BYTES + o);
                }
                CP_COMMIT();
            }
#pragma unroll
            for (int it = 0; it < 8; ++it)
                xv[it] = *reinterpret_cast<const float4*>(xbase + (size_t)c0 * KCHUNK + (size_t)(it * 16) * HIDDEN);
            cvt_store_a(smem, 0, xv, sts_off, 0, 8);
            if (two) CP_WAIT1(); else CP_WAIT0();
            __syncthreads();
        }

        // ---------------- segment main loop ----------------
        int bufB = 0, bufA = 0;
        for (int c = c0; c < c1; ++c) {
            const bool more = (c + 1 < c1);
            if (c + 2 < c1) {
                int bw = bufB + 2; if (bw >= 3) bw -= 3;
                const size_t bo = (size_t)(c + 2) * BTILE_BYTES;
#pragma unroll
                for (int i = 0; i < 5; ++i) {
                    uint32_t o = (uint32_t)(i * 256 + tid) * 16;
                    CP_ASYNC16(sb + SB_OFF(bw, 0) + o, g_whi + bo + o);
                    CP_ASYNC16(sb + SB_OFF(bw, 1) + o, g_wlo + bo + o);
                }
                CP_COMMIT();
            }
            if (more) {
                const float* xc = xbase + (size_t)(c + 1) * KCHUNK;
#pragma unroll
                for (int it = 0; it < 8; ++it)
                    xv[it] = *reinterpret_cast<const float4*>(xc + (size_t)(it * 16) * HIDDEN);
            }

            const uint32_t aHi = sb + SA_OFF(bufA, 0);
            const uint32_t aLo = sb + SA_OFF(bufA, 1);
            const uint32_t bHi = sb + SB_OFF(bufB, 0);
            const uint32_t bLo = sb + SB_OFF(bufB, 1);

#pragma unroll
            for (int s = 0; s < 4; ++s) {
                const int sidx = (s + swoff) & 3;
                uint32_t bh[10], bl[10];
#pragma unroll
                for (int p = 0; p < 2; ++p) {
                    uint32_t seg = (uint32_t)(2 * sidx + b_segadd) << 4;
                    uint32_t off = b_row_off[p] + (seg ^ b_swm[p]);
                    LDSM_X4(bh[4 * p + 0], bh[4 * p + 1], bh[4 * p + 2], bh[4 * p + 3], bHi + off);
                    LDSM_X4(bl[4 * p + 0], bl[4 * p + 1], bl[4 * p + 2], bl[4 * p + 3], bLo + off);
                }
                {
                    uint32_t seg = (uint32_t)(2 * sidx + b2_segadd) << 4;
                    uint32_t off = b2_row_off + (seg ^ b2_swm);
                    LDSM_X2(bh[8], bh[9], bHi + off);
                    LDSM_X2(bl[8], bl[9], bLo + off);
                }
#pragma unroll
                for (int mi = 0; mi < 4; ++mi) {
                    uint32_t seg = (uint32_t)(2 * sidx + a_segadd) << 4;
                    uint32_t off = a_row_off[mi] + (seg ^ a_swm[mi]);
                    uint32_t ah0, ah1, ah2, ah3, al0, al1, al2, al3;
                    LDSM_X4(ah0, ah1, ah2, ah3, aHi + off);
                    LDSM_X4(al0, al1, al2, al3, aLo + off);
#pragma unroll
                    for (int nj = 0; nj < 5; ++nj)
                        MMA_F32(facc[mi][nj], ah0, ah1, ah2, ah3, bh[2 * nj], bh[2 * nj + 1]);
#pragma unroll
                    for (int nj = 0; nj < 5; ++nj)
                        MMA_F16(hacc[mi][nj], ah0, ah1, ah2, ah3, bl[2 * nj], bl[2 * nj + 1]);
#pragma unroll
                    for (int nj = 0; nj < 5; ++nj)
                        MMA_F16(hacc[mi][nj], al0, al1, al2, al3, bh[2 * nj], bh[2 * nj + 1]);
                }
                if (s == 1 && more) cvt_store_a(smem, bufA ^ 1, xv, sts_off, 0, 4);
                if (s == 3 && more) cvt_store_a(smem, bufA ^ 1, xv, sts_off, 4, 8);
            }

            if (c + 2 < c1)      CP_WAIT1();
            else if (c + 1 < c1) CP_WAIT0();
            __syncthreads();
            bufA ^= 1;
            bufB += 1; if (bufB >= 3) bufB -= 3;
        }

        // ---------------- write partial logits to global slot ---------------
        const int b0own = owner(NCHUNKS * t);
        const int slot  = bid - b0own;
        float* gp = g_part + ((size_t)t * 2 + slot) * (128 * NEXP);
#pragma unroll
        for (int mi = 0; mi < 4; ++mi) {
            int r0 = wm * 64 + mi * 16 + (lane >> 2);
#pragma unroll
            for (int nj = 0; nj < 5; ++nj) {
                int cb = wn * 40 + nj * 8 + (lane & 3) * 2;
                float2 c0v = __half22float2(*reinterpret_cast<__half2*>(&hacc[mi][nj][0]));
                float2 c1v = __half22float2(*reinterpret_cast<__half2*>(&hacc[mi][nj][1]));
                *reinterpret_cast<float2*>(gp + (size_t)r0 * NEXP + cb) =
                    make_float2(facc[mi][nj][0] + c0v.x * LO_INV,
                                facc[mi][nj][1] + c0v.y * LO_INV);
                *reinterpret_cast<float2*>(gp + (size_t)(r0 + 8) * NEXP + cb) =
                    make_float2(facc[mi][nj][2] + c1v.x * LO_INV,
                                facc[mi][nj][3] + c1v.y * LO_INV);
            }
        }
        __threadfence();
        if (tid == 0) {
            int nctr = owner(NCHUNKS * t + NCHUNKS - 1) - b0own + 1;
            int old = atomicAdd(&g_done[t], 1);
            flag_s = (old == nctr - 1) ? nctr : 0;
        }
        __syncthreads();
        const int n_contrib = flag_s;

        // ---------------- epilogue (last finisher only) ----------------------
        if (n_contrib) {
            __threadfence();
            float* red = reinterpret_cast<float*>(smem + RED_OFF);
            float* g8  = reinterpret_cast<float*>(smem + G8_OFF);
            const int tok = tid & 127;
            const int seg = tid >> 7;
            const int e0  = seg * 80;
            const float* gp0 = g_part + (size_t)t * 2 * (128 * NEXP) + (size_t)tok * NEXP + e0;

            float z[80];
#pragma unroll
            for (int j = 0; j < 80; j += 2) {
                float2 v = __ldcg(reinterpret_cast<const float2*>(gp0 + j));
                if (n_contrib == 2) {
                    float2 v2 = __ldcg(reinterpret_cast<const float2*>(gp0 + 128 * NEXP + j));
                    v.x += v2.x; v.y += v2.y;
                }
                z[j] = v.x; z[j + 1] = v.y;
            }

            float mx = -3.4e38f;
#pragma unroll
            for (int j = 0; j < 80; ++j) mx = fmaxf(mx, z[j]);
            red[seg * 128 + tok] = mx;
            __syncthreads();
            mx = fmaxf(red[tok], red[128 + tok]);
            __syncthreads();

            float sum = 0.f;
#pragma unroll
            for (int j = 0; j < 80; ++j) {
                float p = __expf(z[j] - mx);
                sum += p;
                z[j] = p;
            }
            red[seg * 128 + tok] = sum;
            __syncthreads();
            sum = red[tok] + red[128 + tok];

            float gm[4];
#pragma unroll
            for (int q = 0; q < 4; ++q) {
                float m = 0.f;
#pragma unroll
                for (int tt = 0; tt < EPG; ++tt) m = fmaxf(m, z[q * EPG + tt]);
                gm[q] = m;
                g8[(seg * 4 + q) * 128 + tok] = m;
            }
            __syncthreads();

            float gv[NGROUP];
#pragma unroll
            for (int q = 0; q < NGROUP; ++q) gv[q] = g8[q * 128 + tok];
            float t1 = 0.f, t2 = 0.f, t3 = 0.f;
#pragma unroll
            for (int q = 0; q < NGROUP; ++q) t1 = fmaxf(t1, gv[q]);
#pragma unroll
            for (int q = 0; q < NGROUP; ++q) t2 = fmaxf(t2, (gv[q] < t1) ? gv[q] : 0.f);
#pragma unroll
            for (int q = 0; q < NGROUP; ++q) t3 = fmaxf(t3, (gv[q] < t2) ? gv[q] : 0.f);

#pragma unroll
            for (int q = 0; q < 4; ++q) {
                float keep = (gm[q] >= t3) ? 1.f : 0.f;
#pragma unroll
                for (int tt = 0; tt < EPG; ++tt) z[q * EPG + tt] *= keep;
            }

            const float inv = 16.0f / sum;
            float* orow = out + (size_t)(m0 + tok) * TOPK;
            float prev = 3.4e38f;
            __syncthreads();
            for (int i = 0; i < TOPK; ++i) {
                float cand = 0.f;
#pragma unroll
                for (int j = 0; j < 80; ++j)
                    cand = fmaxf(cand, (z[j] < prev) ? z[j] : 0.f);
                red[seg * 128 + tok] = cand;
                __syncthreads();
                float cur = fmaxf(red[tok], red[128 + tok]);
                __syncthreads();
                if (seg == 0) orow[i] = cur * inv;
                prev = cur;
            }
        }

        w = NCHUNKS * t + c1;
    }
}

// ---------------- launch ----------------------------------------------------
extern "C" void kernel_launch(void* const* d_in, const int* in_sizes, int n_in,
                              void* d_out, int out_size) {
    const float* x = (const float*)d_in[0];   // [32768, 5120] fp32
    const float* w = (const float*)d_in[1];   // [160, 5120] fp32
    float* out = (float*)d_out;               // [32768, 6] fp32

    cudaFuncSetAttribute(moe_gate_kernel,
                         cudaFuncAttributeMaxDynamicSharedMemorySize, SMEM_BYTES);

    int prep_elems = NEXP * (HIDDEN / 8);
    prep_w_kernel<<<(prep_elems + 255) / 256, 256>>>(w);
    moe_gate_kernel<<<148, NTHREADS, SMEM_BYTES>>>(x, out);
}